// round 5
// baseline (speedup 1.0000x reference)
#include <cuda_runtime.h>
#include <math.h>

// ---------------------------------------------------------------------------
// HyperNetworkDecoder: K=2, P=4096, 8 layers of width 64.
// hyper_kernel generates per-(k,layer) weights ONCE (chunk constant across P),
// written TRANSPOSED ([m][n]).  decode_kernel: all weights in smem (single
// block barrier), 1024-thread blocks (32 warps/SM) for latency hiding;
// warp owns 2 points, 16 lanes/point, shuffle LayerNorm.
// ---------------------------------------------------------------------------

#define KB 2

__device__ __align__(16) float g_W0[KB * 128 * 64];      // layer0 W^T [k][m pad128][n]
__device__ __align__(16) float g_Wl[KB * 7 * 64 * 64];   // layers 1..7 W^T [k][l-1][m][n]
__device__ __align__(16) float g_b [KB * 8 * 64];        // biases [k][l][n]

// ---------------------------------------------------------------------------
// Kernel 1: hypernetwork. grid = (k,l) x 16 output-splits = 256 blocks.
// ---------------------------------------------------------------------------
__global__ void __launch_bounds__(256) hyper_kernel(
    const float* __restrict__ latent_tokens,
    const float* __restrict__ token_embeddings,
    const float* __restrict__ h_W0,  const float* __restrict__ h_b0,
    const float* __restrict__ h_ln_s0, const float* __restrict__ h_ln_b0,
    const float* __restrict__ w_W0,  const float* __restrict__ w_b0,
    const float* __restrict__ bb_W0, const float* __restrict__ bb_b0,
    const float* __restrict__ h_W,   const float* __restrict__ h_b,
    const float* __restrict__ h_ln_s, const float* __restrict__ h_ln_b,
    const float* __restrict__ w_W,   const float* __restrict__ w_b,
    const float* __restrict__ bb_W,  const float* __restrict__ bb_b)
{
    __shared__ float chunk[128];
    __shared__ float part[4][64];
    __shared__ float pre[64];
    __shared__ float hbuf[64];

    const int tid = threadIdx.x;
    const int bx  = blockIdx.x;
    const int sp  = bx & 15;
    const int kl  = bx >> 4;
    const int k   = kl >> 3;
    const int l   = kl & 7;

    if (tid < 128)
        chunk[tid] = (tid < 64) ? latent_tokens[(k * 8 + l) * 64 + tid]
                                : token_embeddings[l * 64 + (tid - 64)];
    __syncthreads();

    const float* hWp = (l == 0) ? h_W0 : (h_W + (l - 1) * 128 * 64);
    {
        const int q = tid >> 6, j = tid & 63;
        float acc = 0.f;
        #pragma unroll
        for (int i = 0; i < 32; i++) {
            int ii = q * 32 + i;
            acc = fmaf(chunk[ii], __ldg(hWp + ii * 64 + j), acc);
        }
        part[q][j] = acc;
    }
    __syncthreads();
    if (tid < 64) {
        float hb = (l == 0) ? __ldg(h_b0 + tid) : __ldg(h_b + (l - 1) * 64 + tid);
        pre[tid] = part[0][tid] + part[1][tid] + part[2][tid] + part[3][tid] + hb;
    }
    __syncthreads();
    if (tid < 64) {
        float s1 = 0.f, s2 = 0.f;
        #pragma unroll 8
        for (int i = 0; i < 64; i++) { float v = pre[i]; s1 += v; s2 += v * v; }
        float mu   = s1 * (1.f / 64.f);
        float var  = s2 * (1.f / 64.f) - mu * mu;
        float rstd = rsqrtf(var + 1e-6f);
        float ls = (l == 0) ? __ldg(h_ln_s0 + tid) : __ldg(h_ln_s + (l - 1) * 64 + tid);
        float lb = (l == 0) ? __ldg(h_ln_b0 + tid) : __ldg(h_ln_b + (l - 1) * 64 + tid);
        float h  = fmaf((pre[tid] - mu) * rstd, ls, lb);
        hbuf[tid] = fmaxf(h, 0.f);
    }
    __syncthreads();

    const int OUT  = (l == 0) ? 8064 : 4096;
    const int CH   = OUT >> 4;
    const int o0   = sp * CH, oend = o0 + CH;
    const float* wWp = (l == 0) ? w_W0 : (w_W + (l - 1) * 64 * 4096);
    const float* wbp = (l == 0) ? w_b0 : (w_b + (l - 1) * 4096);

    float acc[2];
    #pragma unroll
    for (int i = 0; i < 2; i++) {
        int o = o0 + tid + i * 256;
        acc[i] = (o < oend) ? __ldg(wbp + o) : 0.f;
    }
    #pragma unroll 8
    for (int j = 0; j < 64; j++) {
        float hj = hbuf[j];
        const float* row = wWp + j * OUT;
        #pragma unroll
        for (int i = 0; i < 2; i++) {
            int o = o0 + tid + i * 256;
            if (o < oend) acc[i] = fmaf(hj, __ldg(row + o), acc[i]);
        }
    }
    // transposed writes: W^T[m][n]
    #pragma unroll
    for (int i = 0; i < 2; i++) {
        int o = o0 + tid + i * 256;
        if (o < oend) {
            if (l == 0) {
                int n = o / 126, m = o - n * 126;          // in=126
                g_W0[k * 8192 + m * 64 + n] = acc[i];
            } else {
                int n = o >> 6, m = o & 63;                // in=64
                g_Wl[k * 28672 + (l - 1) * 4096 + m * 64 + n] = acc[i];
            }
        }
    }

    if (sp == 0) {
        if (l == 0 && tid < 128)                            // zero pad rows m=126,127
            g_W0[k * 8192 + 8064 + tid] = 0.f;
        if (tid < 64) {
            const float* bWp = (l == 0) ? bb_W0 : (bb_W + (l - 1) * 64 * 64);
            float accb = (l == 0) ? __ldg(bb_b0 + tid) : __ldg(bb_b + (l - 1) * 64 + tid);
            #pragma unroll 8
            for (int j = 0; j < 64; j++)
                accb = fmaf(hbuf[j], __ldg(bWp + j * 64 + tid), accb);
            g_b[(k * 8 + l) * 64 + tid] = accb;
        }
    }
}

// ---------------------------------------------------------------------------
// Float-only accurate sin: 2-term Cody-Waite reduction by pi, then sinf.
// ---------------------------------------------------------------------------
__device__ __forceinline__ float acc_sin(float x)
{
    float q = rintf(x * 0.318309886183790672f);
    float r = fmaf(-q, 3.14159274101257324f, x);
    r = fmaf(-q, -8.74227800037e-8f, r);
    float s = sinf(r);
    return (((int)q) & 1) ? -s : s;
}

// acc4 += xs * w4 (scalar x vector)
#define FMAS4(A, XS, W) do { \
    (A).x = fmaf((XS), (W).x, (A).x); (A).y = fmaf((XS), (W).y, (A).y); \
    (A).z = fmaf((XS), (W).z, (A).z); (A).w = fmaf((XS), (W).w, (A).w); } while (0)

// ---------------------------------------------------------------------------
// Kernel 2: decoder. 128 blocks x 1024 threads, 64 points/block (one k).
// Warp w owns points 2w, 2w+1. Lane (t in [0,16), c = lane>>4):
//   computes outputs [4t, 4t+4) of point 2w+c.
// All weights in smem ([m][n] transposed, conflict-free float4 reads);
// single __syncthreads after load; per-layer sync is warp-local.
// 32 warps/SM -> latency of LDS + shuffle-LN hidden across warps.
// ---------------------------------------------------------------------------
__global__ void __launch_bounds__(1024, 1) decode_kernel(
    const float* __restrict__ rays,
    const float* __restrict__ ln_s0, const float* __restrict__ ln_b0,
    const float* __restrict__ ln_s,  const float* __restrict__ ln_b,
    const float* __restrict__ rgb_W, const float* __restrict__ rgb_b,
    float* __restrict__ out)
{
    extern __shared__ float smem[];
    float4* sW0 = (float4*)smem;            // 2048 float4  (W0^T 128x64)
    float4* sWl = sW0 + 2048;               // 7168 float4  (7 x 64x64)
    float*  xs  = (float*)(sW0 + 9216);     // 64 rows * 132 floats

    const int tid  = threadIdx.x;
    const int w    = tid >> 5;
    const int lane = tid & 31;
    const int t    = lane & 15;
    const int c    = lane >> 4;
    const int n0   = t * 4;
    const int k    = blockIdx.x >> 6;
    const int pt   = 2 * w + c;
    const int gpt  = blockIdx.x * 64 + pt;

    // ---- weight load (coalesced, 9 float4 per thread) ----
    {
        const float4* s0 = (const float4*)g_W0 + k * 2048;
        const float4* s1 = (const float4*)g_Wl + k * 7168;
        #pragma unroll
        for (int i = 0; i < 2; i++) sW0[tid + i * 1024] = __ldg(s0 + tid + i * 1024);
        #pragma unroll
        for (int i = 0; i < 7; i++) sWl[tid + i * 1024] = __ldg(s1 + tid + i * 1024);
    }

    // ---- positional encoding: 16 lanes per point; lane t<10 -> freq t ----
    {
        float* xrow = xs + pt * 132;
        const float* r = rays + gpt * 6;
        float ox = __ldg(r + 0), oy = __ldg(r + 1), oz = __ldg(r + 2);
        float dx = __ldg(r + 3), dy = __ldg(r + 4), dz = __ldg(r + 5);
        float pl[6];
        pl[0] = dx; pl[1] = dy; pl[2] = dz;
        pl[3] = oy * dz - oz * dy;
        pl[4] = oz * dx - ox * dz;
        pl[5] = ox * dy - oy * dx;
        if (t == 10) {
            #pragma unroll
            for (int cm = 0; cm < 6; cm++) xrow[cm] = pl[cm];
        }
        if (t == 11) { xrow[126] = 0.f; xrow[127] = 0.f; }
        if (t < 10) {
            const float PIH = 1.57079632679489662f;
            float fr = (float)(1 << t);
            #pragma unroll
            for (int cm = 0; cm < 6; cm++) {
                float a = pl[cm] * fr;
                xrow[6 + t * 6 + cm]  = acc_sin(a);
                xrow[66 + t * 6 + cm] = acc_sin(a + PIH);
            }
        }
    }
    __syncthreads();   // the ONLY block barrier

    const float*  bb = g_b + k * 512;
    float*        xr = xs + pt * 132;
    const float4* x4 = (const float4*)xr;

    float4 a;

    #pragma unroll 1
    for (int l = 0; l < 8; l++) {
        const float4* Wt = (l == 0) ? sW0 : (sWl + (l - 1) * 1024);
        const int M4 = (l == 0) ? 32 : 16;

        a = __ldg((const float4*)(bb + l * 64 + n0));

        #pragma unroll 4
        for (int m4 = 0; m4 < M4; m4++) {
            float4 x  = x4[m4];
            float4 w0 = Wt[(m4 * 4 + 0) * 16 + t];
            float4 w1 = Wt[(m4 * 4 + 1) * 16 + t];
            float4 w2 = Wt[(m4 * 4 + 2) * 16 + t];
            float4 w3 = Wt[(m4 * 4 + 3) * 16 + t];
            FMAS4(a, x.x, w0);
            FMAS4(a, x.y, w1);
            FMAS4(a, x.z, w2);
            FMAS4(a, x.w, w3);
        }

        // 16-lane shuffle LayerNorm (per point)
        float s1 = a.x + a.y + a.z + a.w;
        float s2 = a.x * a.x + a.y * a.y + a.z * a.z + a.w * a.w;
        #pragma unroll
        for (int m = 1; m < 16; m <<= 1) {
            s1 += __shfl_xor_sync(0xffffffffu, s1, m, 32);
            s2 += __shfl_xor_sync(0xffffffffu, s2, m, 32);
        }
        float mu = s1 * (1.f / 64.f);
        float rs = rsqrtf(s2 * (1.f / 64.f) - mu * mu + 1e-6f);

        const float* lns = (l == 0) ? ln_s0 : (ln_s + (l - 1) * 64);
        const float* lnb = (l == 0) ? ln_b0 : (ln_b + (l - 1) * 64);
        float4 ls4 = __ldg((const float4*)(lns + n0));
        float4 lb4 = __ldg((const float4*)(lnb + n0));

        a.x = fmaxf(fmaf((a.x - mu) * rs, ls4.x, lb4.x), 0.f);
        a.y = fmaxf(fmaf((a.y - mu) * rs, ls4.y, lb4.y), 0.f);
        a.z = fmaxf(fmaf((a.z - mu) * rs, ls4.z, lb4.z), 0.f);
        a.w = fmaxf(fmaf((a.w - mu) * rs, ls4.w, lb4.w), 0.f);

        if (l < 7) {
            ((float4*)xr)[t] = a;
            __syncwarp();
        }
    }

    // ---- rgb head + sigmoid (reduce 16 lanes via shuffle) ----
    {
        float r0 = 0.f, r1 = 0.f, r2 = 0.f;
        #pragma unroll
        for (int j = 0; j < 4; j++) {
            float v = (j == 0) ? a.x : (j == 1) ? a.y : (j == 2) ? a.z : a.w;
            r0 = fmaf(v, __ldg(rgb_W + (n0 + j) * 3 + 0), r0);
            r1 = fmaf(v, __ldg(rgb_W + (n0 + j) * 3 + 1), r1);
            r2 = fmaf(v, __ldg(rgb_W + (n0 + j) * 3 + 2), r2);
        }
        #pragma unroll
        for (int m = 1; m < 16; m <<= 1) {
            r0 += __shfl_xor_sync(0xffffffffu, r0, m, 32);
            r1 += __shfl_xor_sync(0xffffffffu, r1, m, 32);
            r2 += __shfl_xor_sync(0xffffffffu, r2, m, 32);
        }
        if (t == 0) {
            out[gpt * 3 + 0] = 1.f / (1.f + expf(-(r0 + __ldg(rgb_b + 0))));
            out[gpt * 3 + 1] = 1.f / (1.f + expf(-(r1 + __ldg(rgb_b + 1))));
            out[gpt * 3 + 2] = 1.f / (1.f + expf(-(r2 + __ldg(rgb_b + 2))));
        }
    }
}

// ---------------------------------------------------------------------------
extern "C" void kernel_launch(void* const* d_in, const int* in_sizes, int n_in,
                              void* d_out, int out_size)
{
    const float* rays    = (const float*)d_in[0];
    const float* lat     = (const float*)d_in[1];
    const float* temb    = (const float*)d_in[2];
    const float* h_W0    = (const float*)d_in[3];
    const float* h_b0    = (const float*)d_in[4];
    const float* h_ln_s0 = (const float*)d_in[5];
    const float* h_ln_b0 = (const float*)d_in[6];
    const float* w_W0    = (const float*)d_in[7];
    const float* w_b0    = (const float*)d_in[8];
    const float* bb_W0   = (const float*)d_in[9];
    const float* bb_b0   = (const float*)d_in[10];
    const float* ln_s0   = (const float*)d_in[11];
    const float* ln_b0   = (const float*)d_in[12];
    const float* h_W     = (const float*)d_in[13];
    const float* h_b     = (const float*)d_in[14];
    const float* h_ln_s  = (const float*)d_in[15];
    const float* h_ln_b  = (const float*)d_in[16];
    const float* w_W     = (const float*)d_in[17];
    const float* w_b     = (const float*)d_in[18];
    const float* bb_W    = (const float*)d_in[19];
    const float* bb_b    = (const float*)d_in[20];
    const float* ln_s    = (const float*)d_in[21];
    const float* ln_b    = (const float*)d_in[22];
    const float* rgb_W   = (const float*)d_in[23];
    const float* rgb_b   = (const float*)d_in[24];
    float* out = (float*)d_out;

    const int SMEM = 9216 * 16 + 64 * 132 * 4;   // 181248 B
    cudaFuncSetAttribute(decode_kernel,
                         cudaFuncAttributeMaxDynamicSharedMemorySize, SMEM);

    hyper_kernel<<<256, 256>>>(lat, temb, h_W0, h_b0, h_ln_s0, h_ln_b0,
                               w_W0, w_b0, bb_W0, bb_b0,
                               h_W, h_b, h_ln_s, h_ln_b,
                               w_W, w_b, bb_W, bb_b);
    decode_kernel<<<128, 1024, SMEM>>>(rays, ln_s0, ln_b0, ln_s, ln_b,
                                       rgb_W, rgb_b, out);
}

// round 6
// speedup vs baseline: 1.5782x; 1.5782x over previous
#include <cuda_runtime.h>
#include <math.h>

// ---------------------------------------------------------------------------
// HyperNetworkDecoder: K=2, P=4096, 8 layers of width 64.
// hyper_kernel: generate per-(k,layer) weights once (chunk constant across P),
// stored transposed [m][n]; j-reduction split across 2 thread groups.
// decode_kernel: all weights in smem; warp = 16 n-lanes x 2 m-halves,
// 4 points per warp in registers -> 64 FFMA per 8 LDS.128 (FMA-pipe bound).
// ---------------------------------------------------------------------------

#define KB 2

__device__ __align__(16) float g_W0[KB * 128 * 64];      // layer0 W^T [k][m pad128][n]
__device__ __align__(16) float g_Wl[KB * 7 * 64 * 64];   // layers 1..7 W^T [k][l-1][m][n]
__device__ __align__(16) float g_b [KB * 8 * 64];        // biases [k][l][n]

// ---------------------------------------------------------------------------
// Kernel 1: hypernetwork. grid = (k,l) x 16 output-splits = 256 blocks,
// 512 threads: 2 j-groups of 256 each handle half the 64-deep reduction.
// ---------------------------------------------------------------------------
__global__ void __launch_bounds__(512) hyper_kernel(
    const float* __restrict__ latent_tokens,
    const float* __restrict__ token_embeddings,
    const float* __restrict__ h_W0,  const float* __restrict__ h_b0,
    const float* __restrict__ h_ln_s0, const float* __restrict__ h_ln_b0,
    const float* __restrict__ w_W0,  const float* __restrict__ w_b0,
    const float* __restrict__ bb_W0, const float* __restrict__ bb_b0,
    const float* __restrict__ h_W,   const float* __restrict__ h_b,
    const float* __restrict__ h_ln_s, const float* __restrict__ h_ln_b,
    const float* __restrict__ w_W,   const float* __restrict__ w_b,
    const float* __restrict__ bb_W,  const float* __restrict__ bb_b)
{
    __shared__ float chunk[128];
    __shared__ float part[4][64];
    __shared__ float pre[64];
    __shared__ float hbuf[64];
    __shared__ float wpart[1024];    // [group][acc-slot][256]

    const int tid = threadIdx.x;
    const int bx  = blockIdx.x;
    const int sp  = bx & 15;
    const int kl  = bx >> 4;
    const int k   = kl >> 3;
    const int l   = kl & 7;

    if (tid < 128)
        chunk[tid] = (tid < 64) ? latent_tokens[(k * 8 + l) * 64 + tid]
                                : token_embeddings[l * 64 + (tid - 64)];
    __syncthreads();

    const float* hWp = (l == 0) ? h_W0 : (h_W + (l - 1) * 128 * 64);
    if (tid < 256) {
        const int q = tid >> 6, j = tid & 63;
        float acc = 0.f;
        #pragma unroll
        for (int i = 0; i < 32; i++) {
            int ii = q * 32 + i;
            acc = fmaf(chunk[ii], __ldg(hWp + ii * 64 + j), acc);
        }
        part[q][j] = acc;
    }
    __syncthreads();
    if (tid < 64) {
        float hb = (l == 0) ? __ldg(h_b0 + tid) : __ldg(h_b + (l - 1) * 64 + tid);
        pre[tid] = part[0][tid] + part[1][tid] + part[2][tid] + part[3][tid] + hb;
    }
    __syncthreads();
    if (tid < 64) {
        float s1 = 0.f, s2 = 0.f;
        #pragma unroll 8
        for (int i = 0; i < 64; i++) { float v = pre[i]; s1 += v; s2 += v * v; }
        float mu   = s1 * (1.f / 64.f);
        float var  = s2 * (1.f / 64.f) - mu * mu;
        float rstd = rsqrtf(var + 1e-6f);
        float ls = (l == 0) ? __ldg(h_ln_s0 + tid) : __ldg(h_ln_s + (l - 1) * 64 + tid);
        float lb = (l == 0) ? __ldg(h_ln_b0 + tid) : __ldg(h_ln_b + (l - 1) * 64 + tid);
        float h  = fmaf((pre[tid] - mu) * rstd, ls, lb);
        hbuf[tid] = fmaxf(h, 0.f);
    }
    __syncthreads();

    const int OUT  = (l == 0) ? 8064 : 4096;
    const int CH   = OUT >> 4;
    const int o0   = sp * CH, oend = o0 + CH;
    const float* wWp = (l == 0) ? w_W0 : (w_W + (l - 1) * 64 * 4096);
    const float* wbp = (l == 0) ? w_b0 : (w_b + (l - 1) * 4096);

    const int g  = tid >> 8;        // j-group 0/1
    const int tt = tid & 255;

    float acc[2];
    #pragma unroll
    for (int i = 0; i < 2; i++) {
        int o = o0 + tt + i * 256;
        acc[i] = (o < oend && g == 0) ? __ldg(wbp + o) : 0.f;
    }
    const int j0 = g * 32;
    #pragma unroll 8
    for (int jj = 0; jj < 32; jj++) {
        float hj = hbuf[j0 + jj];
        const float* row = wWp + (j0 + jj) * OUT;
        #pragma unroll
        for (int i = 0; i < 2; i++) {
            int o = o0 + tt + i * 256;
            if (o < oend) acc[i] = fmaf(hj, __ldg(row + o), acc[i]);
        }
    }
    wpart[g * 512 + tt]       = acc[0];
    wpart[g * 512 + 256 + tt] = acc[1];
    __syncthreads();

    if (g == 0) {
        #pragma unroll
        for (int i = 0; i < 2; i++) {
            int o = o0 + tt + i * 256;
            if (o < oend) {
                float v = acc[i] + wpart[512 + i * 256 + tt];
                if (l == 0) {
                    int n = o / 126, m = o - n * 126;          // in=126
                    g_W0[k * 8192 + m * 64 + n] = v;
                } else {
                    int n = o >> 6, m = o & 63;                // in=64
                    g_Wl[k * 28672 + (l - 1) * 4096 + m * 64 + n] = v;
                }
            }
        }
    }

    if (sp == 0) {
        if (l == 0 && tid < 128)                               // zero-pad m=126,127
            g_W0[k * 8192 + 8064 + tid] = 0.f;
        if (tid < 64) {
            const float* bWp = (l == 0) ? bb_W0 : (bb_W + (l - 1) * 64 * 64);
            float accb = (l == 0) ? __ldg(bb_b0 + tid) : __ldg(bb_b + (l - 1) * 64 + tid);
            #pragma unroll 8
            for (int j = 0; j < 64; j++)
                accb = fmaf(hbuf[j], __ldg(bWp + j * 64 + tid), accb);
            g_b[(k * 8 + l) * 64 + tid] = accb;
        }
    }
}

// ---------------------------------------------------------------------------
// Float-only accurate sin: 2-term Cody-Waite reduction by pi, then sinf.
// ---------------------------------------------------------------------------
__device__ __forceinline__ float acc_sin(float x)
{
    float q = rintf(x * 0.318309886183790672f);
    float r = fmaf(-q, 3.14159274101257324f, x);
    r = fmaf(-q, -8.74227800037e-8f, r);
    float s = sinf(r);
    return (((int)q) & 1) ? -s : s;
}

// acc4 += xs * w4 (scalar x vector)
#define FMAS4(A, XS, W) do { \
    (A).x = fmaf((XS), (W).x, (A).x); (A).y = fmaf((XS), (W).y, (A).y); \
    (A).z = fmaf((XS), (W).z, (A).z); (A).w = fmaf((XS), (W).w, (A).w); } while (0)

// One m-half of one layer for 4 points: HALF m4-iterations.
template<int HALF>
__device__ __forceinline__ void layer_mm(
    const float4* __restrict__ Wt, const float* __restrict__ xbase,
    int m4lo, int t, float4 acc[4])
{
    #pragma unroll
    for (int i = 0; i < HALF; i++) {
        int m4 = m4lo + i;
        float4 w0 = Wt[(m4 * 4 + 0) * 16 + t];
        float4 w1 = Wt[(m4 * 4 + 1) * 16 + t];
        float4 w2 = Wt[(m4 * 4 + 2) * 16 + t];
        float4 w3 = Wt[(m4 * 4 + 3) * 16 + t];
        #pragma unroll
        for (int p = 0; p < 4; p++) {
            float4 x = ((const float4*)(xbase + p * 132))[m4];
            FMAS4(acc[p], x.x, w0);
            FMAS4(acc[p], x.y, w1);
            FMAS4(acc[p], x.z, w2);
            FMAS4(acc[p], x.w, w3);
        }
    }
}

// ---------------------------------------------------------------------------
// Kernel 2: decoder. 128 blocks x 512 threads, 64 points/block (one k).
// Warp wp owns points 4wp..4wp+3. Lane (t = lane&15, h = lane>>4):
//   computes outputs [4t,4t+4) of all 4 points over m-half h.
// Halves combined via shfl_xor(16); LN via 4-level shuffle; single block
// barrier after weight load.
// ---------------------------------------------------------------------------
__global__ void __launch_bounds__(512, 1) decode_kernel(
    const float* __restrict__ rays,
    const float* __restrict__ ln_s0, const float* __restrict__ ln_b0,
    const float* __restrict__ ln_s,  const float* __restrict__ ln_b,
    const float* __restrict__ rgb_W, const float* __restrict__ rgb_b,
    float* __restrict__ out)
{
    extern __shared__ float smem[];
    float4* sW0 = (float4*)smem;            // 2048 float4  (W0^T 128x64)
    float4* sWl = sW0 + 2048;               // 7168 float4  (7 x 64x64)
    float*  xs  = (float*)(sW0 + 9216);     // 64 rows * 132 floats

    const int tid  = threadIdx.x;
    const int wp   = tid >> 5;
    const int lane = tid & 31;
    const int t    = lane & 15;
    const int h    = lane >> 4;
    const int n0   = t * 4;
    const int k    = blockIdx.x >> 6;
    const int P0   = 4 * wp;

    // ---- weight load (coalesced, 18 float4 per thread) ----
    {
        const float4* s0 = (const float4*)g_W0 + k * 2048;
        const float4* s1 = (const float4*)g_Wl + k * 7168;
        #pragma unroll
        for (int i = 0; i < 4; i++) sW0[tid + i * 512] = __ldg(s0 + tid + i * 512);
        #pragma unroll
        for (int i = 0; i < 14; i++) sWl[tid + i * 512] = __ldg(s1 + tid + i * 512);
    }

    // ---- positional encoding: 8 lanes per point (q = lane>>3, s = lane&7) ----
    {
        const int q  = lane >> 3;
        const int s  = lane & 7;
        const int pt = P0 + q;
        float* xrow  = xs + pt * 132;
        const float* r = rays + (blockIdx.x * 64 + pt) * 6;
        float ox = __ldg(r + 0), oy = __ldg(r + 1), oz = __ldg(r + 2);
        float dx = __ldg(r + 3), dy = __ldg(r + 4), dz = __ldg(r + 5);
        float pl[6];
        pl[0] = dx; pl[1] = dy; pl[2] = dz;
        pl[3] = oy * dz - oz * dy;
        pl[4] = oz * dx - ox * dz;
        pl[5] = ox * dy - oy * dx;
        if (s == 6) {
            #pragma unroll
            for (int cm = 0; cm < 6; cm++) xrow[cm] = pl[cm];
        }
        if (s == 7) { xrow[126] = 0.f; xrow[127] = 0.f; }
        const float PIH = 1.57079632679489662f;
        for (int f = s; f < 10; f += 8) {
            float fr = (float)(1 << f);
            #pragma unroll
            for (int cm = 0; cm < 6; cm++) {
                float a = pl[cm] * fr;
                xrow[6 + f * 6 + cm]  = acc_sin(a);
                xrow[66 + f * 6 + cm] = acc_sin(a + PIH);
            }
        }
    }
    __syncthreads();   // the ONLY block barrier

    const float* bb    = g_b + k * 512;
    const float* xbase = xs + P0 * 132;

    float4 acc[4];

    #pragma unroll 1
    for (int l = 0; l < 8; l++) {
        float4 b4 = __ldg((const float4*)(bb + l * 64 + n0));
        float4 ini = h ? make_float4(0.f, 0.f, 0.f, 0.f) : b4;
        #pragma unroll
        for (int p = 0; p < 4; p++) acc[p] = ini;

        if (l == 0) layer_mm<16>(sW0, xbase, h * 16, t, acc);
        else        layer_mm<8>(sWl + (l - 1) * 1024, xbase, h * 8, t, acc);

        // combine m-halves
        #pragma unroll
        for (int p = 0; p < 4; p++) {
            acc[p].x += __shfl_xor_sync(0xffffffffu, acc[p].x, 16, 32);
            acc[p].y += __shfl_xor_sync(0xffffffffu, acc[p].y, 16, 32);
            acc[p].z += __shfl_xor_sync(0xffffffffu, acc[p].z, 16, 32);
            acc[p].w += __shfl_xor_sync(0xffffffffu, acc[p].w, 16, 32);
        }

        const float* lns = (l == 0) ? ln_s0 : (ln_s + (l - 1) * 64);
        const float* lnb = (l == 0) ? ln_b0 : (ln_b + (l - 1) * 64);
        float4 ls4 = __ldg((const float4*)(lns + n0));
        float4 lb4 = __ldg((const float4*)(lnb + n0));

        #pragma unroll
        for (int p = 0; p < 4; p++) {
            float s1 = acc[p].x + acc[p].y + acc[p].z + acc[p].w;
            float s2 = acc[p].x * acc[p].x + acc[p].y * acc[p].y
                     + acc[p].z * acc[p].z + acc[p].w * acc[p].w;
            #pragma unroll
            for (int m = 1; m < 16; m <<= 1) {
                s1 += __shfl_xor_sync(0xffffffffu, s1, m, 32);
                s2 += __shfl_xor_sync(0xffffffffu, s2, m, 32);
            }
            float mu = s1 * (1.f / 64.f);
            float rs = rsqrtf(s2 * (1.f / 64.f) - mu * mu + 1e-6f);
            acc[p].x = fmaxf(fmaf((acc[p].x - mu) * rs, ls4.x, lb4.x), 0.f);
            acc[p].y = fmaxf(fmaf((acc[p].y - mu) * rs, ls4.y, lb4.y), 0.f);
            acc[p].z = fmaxf(fmaf((acc[p].z - mu) * rs, ls4.z, lb4.z), 0.f);
            acc[p].w = fmaxf(fmaf((acc[p].w - mu) * rs, ls4.w, lb4.w), 0.f);
        }

        if (l < 7) {
            if (h == 0) {
                #pragma unroll
                for (int p = 0; p < 4; p++)
                    ((float4*)(xs + (P0 + p) * 132))[t] = acc[p];
            }
            __syncwarp();
        }
    }

    // ---- rgb head + sigmoid ----
    {
        float wc0[4], wc1[4], wc2[4];
        #pragma unroll
        for (int j = 0; j < 4; j++) {
            wc0[j] = __ldg(rgb_W + (n0 + j) * 3 + 0);
            wc1[j] = __ldg(rgb_W + (n0 + j) * 3 + 1);
            wc2[j] = __ldg(rgb_W + (n0 + j) * 3 + 2);
        }
        float r0[4], r1[4], r2[4];
        #pragma unroll
        for (int p = 0; p < 4; p++) {
            float vx = acc[p].x, vy = acc[p].y, vz = acc[p].z, vw = acc[p].w;
            r0[p] = vx * wc0[0] + vy * wc0[1] + vz * wc0[2] + vw * wc0[3];
            r1[p] = vx * wc1[0] + vy * wc1[1] + vz * wc1[2] + vw * wc1[3];
            r2[p] = vx * wc2[0] + vy * wc2[1] + vz * wc2[2] + vw * wc2[3];
        }
        #pragma unroll
        for (int m = 1; m < 16; m <<= 1) {
            #pragma unroll
            for (int p = 0; p < 4; p++) {
                r0[p] += __shfl_xor_sync(0xffffffffu, r0[p], m, 32);
                r1[p] += __shfl_xor_sync(0xffffffffu, r1[p], m, 32);
                r2[p] += __shfl_xor_sync(0xffffffffu, r2[p], m, 32);
            }
        }
        if (lane < 4) {
            int gpt = blockIdx.x * 64 + P0 + lane;
            float b0 = __ldg(rgb_b + 0), b1 = __ldg(rgb_b + 1), b2 = __ldg(rgb_b + 2);
            out[gpt * 3 + 0] = 1.f / (1.f + expf(-(r0[lane] + b0)));
            out[gpt * 3 + 1] = 1.f / (1.f + expf(-(r1[lane] + b1)));
            out[gpt * 3 + 2] = 1.f / (1.f + expf(-(r2[lane] + b2)));
        }
    }
}

// ---------------------------------------------------------------------------
extern "C" void kernel_launch(void* const* d_in, const int* in_sizes, int n_in,
                              void* d_out, int out_size)
{
    const float* rays    = (const float*)d_in[0];
    const float* lat     = (const float*)d_in[1];
    const float* temb    = (const float*)d_in[2];
    const float* h_W0    = (const float*)d_in[3];
    const float* h_b0    = (const float*)d_in[4];
    const float* h_ln_s0 = (const float*)d_in[5];
    const float* h_ln_b0 = (const float*)d_in[6];
    const float* w_W0    = (const float*)d_in[7];
    const float* w_b0    = (const float*)d_in[8];
    const float* bb_W0   = (const float*)d_in[9];
    const float* bb_b0   = (const float*)d_in[10];
    const float* ln_s0   = (const float*)d_in[11];
    const float* ln_b0   = (const float*)d_in[12];
    const float* h_W     = (const float*)d_in[13];
    const float* h_b     = (const float*)d_in[14];
    const float* h_ln_s  = (const float*)d_in[15];
    const float* h_ln_b  = (const float*)d_in[16];
    const float* w_W     = (const float*)d_in[17];
    const float* w_b     = (const float*)d_in[18];
    const float* bb_W    = (const float*)d_in[19];
    const float* bb_b    = (const float*)d_in[20];
    const float* ln_s    = (const float*)d_in[21];
    const float* ln_b    = (const float*)d_in[22];
    const float* rgb_W   = (const float*)d_in[23];
    const float* rgb_b   = (const float*)d_in[24];
    float* out = (float*)d_out;

    const int SMEM = 9216 * 16 + 64 * 132 * 4;   // 181248 B
    cudaFuncSetAttribute(decode_kernel,
                         cudaFuncAttributeMaxDynamicSharedMemorySize, SMEM);

    hyper_kernel<<<256, 512>>>(lat, temb, h_W0, h_b0, h_ln_s0, h_ln_b0,
                               w_W0, w_b0, bb_W0, bb_b0,
                               h_W, h_b, h_ln_s, h_ln_b,
                               w_W, w_b, bb_W, bb_b);
    decode_kernel<<<128, 512, SMEM>>>(rays, ln_s0, ln_b0, ln_s, ln_b,
                                      rgb_W, rgb_b, out);
}